// round 3
// baseline (speedup 1.0000x reference)
#include <cuda_runtime.h>
#include <math.h>

#define NH 8
#define NHM 8
#define NHS 16
#define NB 2
#define NSEQ 384
#define NCM 16
#define NCS 64
#define NCZ 128
#define NCH 144            // per-head channels: 128 mv (8 mv-ch x 16 comps) + 16 scalar
#define BIGF 100000.0f
#define LNEPS 1e-5f

// Scratch (no cudaMalloc allowed)
__device__ float g_Q[NB*NH*NSEQ*NCH];
__device__ float g_K[NB*NH*NSEQ*NCH];
__device__ float g_V[NB*NH*NSEQ*NCH];
__device__ float g_bias[NB*NH*NSEQ*NSEQ];
__device__ float g_Hb[NB*NSEQ*NH*NCH];

// ---------------- reductions ----------------
__device__ __forceinline__ float warpSum(float v){
#pragma unroll
    for(int o=16;o;o>>=1) v += __shfl_xor_sync(0xffffffffu, v, o);
    return v;
}

template<int NW>
__device__ __forceinline__ float blockSum(float v, float* red){
    int lane = threadIdx.x & 31, w = threadIdx.x >> 5;
    v = warpSum(v);
    if(lane==0) red[w] = v;
    __syncthreads();
    if(threadIdx.x < 32){
        float r = (lane < NW) ? red[lane] : 0.0f;
        r = warpSum(r);
        if(lane==0) red[0] = r;
    }
    __syncthreads();
    float r = red[0];
    __syncthreads();
    return r;
}

template<int NW>
__device__ __forceinline__ float blockMax(float v, float* red){
    int lane = threadIdx.x & 31, w = threadIdx.x >> 5;
#pragma unroll
    for(int o=16;o;o>>=1) v = fmaxf(v, __shfl_xor_sync(0xffffffffu, v, o));
    if(lane==0) red[w] = v;
    __syncthreads();
    if(threadIdx.x < 32){
        float r = (lane < NW) ? red[lane] : -1e30f;
#pragma unroll
        for(int o=16;o;o>>=1) r = fmaxf(r, __shfl_xor_sync(0xffffffffu, r, o));
        if(lane==0) red[0] = r;
    }
    __syncthreads();
    float r = red[0];
    __syncthreads();
    return r;
}

// ---------------- Kernel A: pln + QKV projections + rope ----------------
// One block per (b, n). 256 threads.
__global__ void qkv_kernel(const float* __restrict__ mv, const float* __restrict__ sca,
                           const float* __restrict__ Wq_mv, const float* __restrict__ Wq_s,
                           const float* __restrict__ Wkv_mv, const float* __restrict__ Wkv_s){
    int bn = blockIdx.x;
    int b = bn / NSEQ, n = bn % NSEQ;
    int t = threadIdx.x;
    __shared__ float mvn[256];
    __shared__ float scn[64];
    __shared__ float qs[128], ks[128], vs[128];
    __shared__ float red[32];
    const float scl = 1.0f/12.0f;  // 1/sqrt(16*HM + HS) = 1/sqrt(144)

    // pln over flattened multivector (256 elems)
    float x = mv[(size_t)bn*256 + t];
    float s1 = blockSum<8>(x, red);
    float s2 = blockSum<8>(x*x, red);
    float m  = s1 * (1.0f/256.0f);
    float vr = s2 * (1.0f/256.0f) - m*m;
    mvn[t] = (x - m) * rsqrtf(vr + LNEPS);

    // pln over scalars (64 elems)
    float y = (t < 64) ? sca[(size_t)bn*64 + t] : 0.0f;
    float t1 = blockSum<8>(y, red);
    float t2 = blockSum<8>(y*y, red);
    float m2 = t1 * (1.0f/64.0f);
    float v2 = t2 * (1.0f/64.0f) - m2*m2;
    float rs2 = rsqrtf(v2 + LNEPS);
    if(t < 64) scn[t] = (y - m2) * rs2;
    __syncthreads();

    // q_mv: 64 outputs x 16 comps; o = m*H + h
    for(int idx = t; idx < 1024; idx += 256){
        int o = idx >> 4, i = idx & 15;
        float a = 0.0f;
#pragma unroll
        for(int c = 0; c < 16; c++) a += mvn[c*16 + i] * Wq_mv[o*16 + c];
        int hh = o & 7, mm = o >> 3;
        g_Q[((b*NH + hh)*NSEQ + n)*NCH + mm*16 + i] = a * scl;
    }
    // kv_mv: 128 outputs x 16 comps; o = kv*64 + m*H + h
    for(int idx = t; idx < 2048; idx += 256){
        int o = idx >> 4, i = idx & 15;
        float a = 0.0f;
#pragma unroll
        for(int c = 0; c < 16; c++) a += mvn[c*16 + i] * Wkv_mv[o*16 + c];
        int kv = o >> 6, rr = o & 63, hh = rr & 7, mm = rr >> 3;
        if(kv == 0) g_K[((b*NH + hh)*NSEQ + n)*NCH + mm*16 + i] = a;
        else        g_V[((b*NH + hh)*NSEQ + n)*NCH + mm*16 + i] = a;
    }
    // q_s: 128 outputs (o = hs*H + h)
    if(t < 128){
        float a = 0.0f;
#pragma unroll
        for(int c = 0; c < 64; c++) a += scn[c] * Wq_s[t*64 + c];
        qs[t] = a;
    }
    // kv_s: 256 outputs (o = kv*128 + hs*H + h)
    {
        float a = 0.0f;
#pragma unroll
        for(int c = 0; c < 64; c++) a += scn[c] * Wkv_s[t*64 + c];
        int kv = t >> 7, rr = t & 127;
        if(kv == 0) ks[rr] = a; else vs[rr] = a;
    }
    __syncthreads();

    // v_s store (no rope)
    if(t < 128){
        int hh = t & 7, ss = t >> 3;
        g_V[((b*NH + hh)*NSEQ + n)*NCH + 128 + ss] = vs[t];
    }
    // rope(q_s) and rope(k_s): d=16 -> 8 pairs per head; inv_p = 4096^(-p/8) = 2^(-1.5p)
    if(t < 64){
        int hh = t & 7, p = t >> 3;
        float ang = (float)n * exp2f(-1.5f * (float)p);
        float cs = cosf(ang), sn = sinf(ang);
        float x1 = qs[(2*p)*8 + hh], x2 = qs[(2*p+1)*8 + hh];
        float* Qr = &g_Q[((b*NH + hh)*NSEQ + n)*NCH + 128];
        Qr[2*p]   = (x1*cs - x2*sn) * scl;
        Qr[2*p+1] = (x1*sn + x2*cs) * scl;
    } else if(t < 128){
        int u = t - 64;
        int hh = u & 7, p = u >> 3;
        float ang = (float)n * exp2f(-1.5f * (float)p);
        float cs = cosf(ang), sn = sinf(ang);
        float x1 = ks[(2*p)*8 + hh], x2 = ks[(2*p+1)*8 + hh];
        float* Kr = &g_K[((b*NH + hh)*NSEQ + n)*NCH + 128];
        Kr[2*p]   = x1*cs - x2*sn;
        Kr[2*p+1] = x1*sn + x2*cs;
    }
}

// ---------------- Kernel B: pair-scalar LN + bias projection ----------------
// One warp per (b,i,j). 8 warps/block, grid = B*N*N/8 exactly.
// Mask read as 4-byte nonzero test: correct for both int32 (1) and float32 (1.0f).
__global__ void bias_kernel(const float* __restrict__ pz, const unsigned int* __restrict__ msk,
                            const float* __restrict__ gamma, const float* __restrict__ beta,
                            const float* __restrict__ Wpb){
    int w = threadIdx.x >> 5, lane = threadIdx.x & 31;
    int pid = blockIdx.x * 8 + w;

    const float4* zp = (const float4*)(pz + (size_t)pid * NCZ);
    float4 z = zp[lane];
    float s1 = z.x + z.y + z.z + z.w;
    float s2 = z.x*z.x + z.y*z.y + z.z*z.z + z.w*z.w;
#pragma unroll
    for(int o=16;o;o>>=1){
        s1 += __shfl_xor_sync(0xffffffffu, s1, o);
        s2 += __shfl_xor_sync(0xffffffffu, s2, o);
    }
    float m  = s1 * (1.0f/NCZ);
    float vr = s2 * (1.0f/NCZ) - m*m;
    float rs = rsqrtf(vr + LNEPS);
    float4 g4 = ((const float4*)gamma)[lane];
    float4 b4 = ((const float4*)beta)[lane];
    float n0 = (z.x - m)*rs*g4.x + b4.x;
    float n1 = (z.y - m)*rs*g4.y + b4.y;
    float n2 = (z.z - m)*rs*g4.z + b4.z;
    float n3 = (z.w - m)*rs*g4.w + b4.w;

    float acc[8];
#pragma unroll
    for(int h = 0; h < 8; h++){
        float4 wv = ((const float4*)(Wpb + h*NCZ))[lane];
        float a = n0*wv.x + n1*wv.y + n2*wv.z + n3*wv.w;
#pragma unroll
        for(int o=16;o;o>>=1) a += __shfl_down_sync(0xffffffffu, a, o);
        acc[h] = a;  // valid in lane 0
    }
    // mask term: reference ADDS (1-mask)*INF.  msk nonzero => mask=1 => 0 added.
    float mb = (msk[pid] != 0u) ? 0.0f : BIGF;

    __shared__ float bt[8][8];
    if(lane == 0){
#pragma unroll
        for(int h = 0; h < 8; h++) bt[w][h] = acc[h] + mb;
    }
    __syncthreads();
    // coalesced-ish store: 8 consecutive j per (b,h,i)
    if(threadIdx.x < 64){
        int h  = threadIdx.x >> 3, ww = threadIdx.x & 7;
        int p2 = blockIdx.x * 8 + ww;
        int b2 = p2 / (NSEQ*NSEQ);
        int r2 = p2 % (NSEQ*NSEQ);
        int i2 = r2 / NSEQ, j2 = r2 % NSEQ;
        g_bias[((b2*NH + h)*NSEQ + i2)*NSEQ + j2] = bt[ww][h];
    }
}

// ---------------- Kernel C: attention ----------------
// One block per (b,h,q). 192 threads (6 warps).
__global__ void attn_kernel(){
    int q = blockIdx.x, h = blockIdx.y, b = blockIdx.z;
    int t = threadIdx.x;
    __shared__ float qv[NCH];
    __shared__ float sc[NSEQ];
    __shared__ float red[32];

    const float* Qr = g_Q + ((size_t)(b*NH + h)*NSEQ + q)*NCH;
    if(t < NCH) qv[t] = Qr[t];
    __syncthreads();

    const float* Kb = g_K + (size_t)(b*NH + h)*NSEQ*NCH;
    const float* bi = g_bias + ((size_t)(b*NH + h)*NSEQ + q)*NSEQ;

    float lmax = -1e30f;
    for(int j = t; j < NSEQ; j += 192){
        const float4* kr = (const float4*)(Kb + (size_t)j*NCH);
        float a0=0,a1=0,a2=0,a3=0;
#pragma unroll
        for(int c = 0; c < 36; c++){
            float4 k4 = kr[c];
            a0 += qv[4*c+0]*k4.x; a1 += qv[4*c+1]*k4.y;
            a2 += qv[4*c+2]*k4.z; a3 += qv[4*c+3]*k4.w;
        }
        float s = (a0+a1) + (a2+a3) + bi[j];
        sc[j] = s;
        lmax = fmaxf(lmax, s);
    }
    float mx = blockMax<6>(lmax, red);
    float lsum = 0.0f;
    for(int j = t; j < NSEQ; j += 192){
        float p = __expf(sc[j] - mx);
        sc[j] = p;
        lsum += p;
    }
    float ssum = blockSum<6>(lsum, red);
    float inv = 1.0f / ssum;

    // AV: channel c per thread, warp-coalesced loads of V[j, c..c+31]
    int c = t;
    if(c < NCH){
        const float* Vb = g_V + (size_t)(b*NH + h)*NSEQ*NCH + c;
        float acc = 0.0f;
#pragma unroll 8
        for(int j = 0; j < NSEQ; j++) acc += sc[j] * Vb[(size_t)j*NCH];
        g_Hb[((size_t)(b*NSEQ + q)*NH + h)*NCH + c] = acc * inv;
    }
}

// ---------------- Kernel D: output projections ----------------
// One block per (b,n). 256 threads.
__global__ void out_kernel(const float* __restrict__ Wo_mv, const float* __restrict__ Wo_s,
                           float* __restrict__ out){
    int bn = blockIdx.x;
    int t = threadIdx.x;
    __shared__ float hrow[NH*NCH];  // 1152
    for(int idx = t; idx < NH*NCH; idx += 256) hrow[idx] = g_Hb[(size_t)bn*NH*NCH + idx];
    __syncthreads();

    // out_mv[b,n,o,i], o<16, i<16; channel c = h*8 + m
    {
        int o = t >> 4, i = t & 15;
        float acc = 0.0f;
#pragma unroll
        for(int hh = 0; hh < 8; hh++)
#pragma unroll
            for(int mm = 0; mm < 8; mm++)
                acc += hrow[hh*NCH + mm*16 + i] * Wo_mv[o*64 + hh*8 + mm];
        out[(size_t)bn*256 + t] = acc;
    }
    // out_s[b,n,o], o<64; channel c = h*16 + s
    if(t < 64){
        float acc = 0.0f;
#pragma unroll
        for(int hh = 0; hh < 8; hh++)
#pragma unroll
            for(int ss = 0; ss < 16; ss++)
                acc += hrow[hh*NCH + 128 + ss] * Wo_s[t*128 + hh*16 + ss];
        out[(size_t)NB*NSEQ*256 + (size_t)bn*64 + t] = acc;
    }
}

// ---------------- launch ----------------
extern "C" void kernel_launch(void* const* d_in, const int* in_sizes, int n_in,
                              void* d_out, int out_size){
    const float* mv    = (const float*)d_in[0];
    const float* sca   = (const float*)d_in[1];
    const float* pz    = (const float*)d_in[2];
    const unsigned int* mask = (const unsigned int*)d_in[3];  // bool -> int32/float32; nonzero test
    const float* Wq_mv = (const float*)d_in[4];
    const float* Wq_s  = (const float*)d_in[5];
    const float* Wkv_mv= (const float*)d_in[6];
    const float* Wkv_s = (const float*)d_in[7];
    const float* Wo_mv = (const float*)d_in[8];
    const float* Wo_s  = (const float*)d_in[9];
    const float* lng   = (const float*)d_in[10];
    const float* lnb   = (const float*)d_in[11];
    const float* Wpb   = (const float*)d_in[12];

    qkv_kernel<<<NB*NSEQ, 256>>>(mv, sca, Wq_mv, Wq_s, Wkv_mv, Wkv_s);
    bias_kernel<<<(NB*NSEQ*NSEQ)/8, 256>>>(pz, mask, lng, lnb, Wpb);
    attn_kernel<<<dim3(NSEQ, NH, NB), 192>>>();
    out_kernel<<<NB*NSEQ, 256>>>(Wo_mv, Wo_s, (float*)d_out);
}

// round 4
// speedup vs baseline: 3.0227x; 3.0227x over previous
#include <cuda_runtime.h>
#include <math.h>

#define NH 8
#define NHM 8
#define NHS 16
#define NB 2
#define NSEQ 384
#define NCZ 128
#define NCH 144            // per-head channels: 128 mv + 16 scalar
#define BIGF 100000.0f
#define LNEPS 1e-5f

#define QT 32              // q tile
#define JT 32              // j tile
#define SQS 148            // Q/K/V tile row stride (floats), 148*4B=592B=37x16B
#define SSS 393            // S row stride (odd -> conflict-free column access)
#define ATTN_SMEM_FLOATS (64*SQS + 32*SSS)

// Scratch (no cudaMalloc allowed)
__device__ float g_Q[NB*NH*NSEQ*NCH];
__device__ float g_K[NB*NH*NSEQ*NCH];
__device__ float g_V[NB*NH*NSEQ*NCH];
__device__ float g_bias[NB*NH*NSEQ*NSEQ];
__device__ float g_Hb[NB*NSEQ*NH*NCH];

// ---------------- reductions ----------------
__device__ __forceinline__ float warpSum(float v){
#pragma unroll
    for(int o=16;o;o>>=1) v += __shfl_xor_sync(0xffffffffu, v, o);
    return v;
}

template<int NW>
__device__ __forceinline__ float blockSum(float v, float* red){
    int lane = threadIdx.x & 31, w = threadIdx.x >> 5;
    v = warpSum(v);
    if(lane==0) red[w] = v;
    __syncthreads();
    if(threadIdx.x < 32){
        float r = (lane < NW) ? red[lane] : 0.0f;
        r = warpSum(r);
        if(lane==0) red[0] = r;
    }
    __syncthreads();
    float r = red[0];
    __syncthreads();
    return r;
}

// ---------------- Kernel A: pln + QKV projections + rope ----------------
// One block per (b, n). 256 threads.
__global__ void qkv_kernel(const float* __restrict__ mv, const float* __restrict__ sca,
                           const float* __restrict__ Wq_mv, const float* __restrict__ Wq_s,
                           const float* __restrict__ Wkv_mv, const float* __restrict__ Wkv_s){
    int bn = blockIdx.x;
    int b = bn / NSEQ, n = bn % NSEQ;
    int t = threadIdx.x;
    __shared__ float mvn[256];
    __shared__ float scn[64];
    __shared__ float qs[128], ks[128], vs[128];
    __shared__ float red[32];
    const float scl = 1.0f/12.0f;  // 1/sqrt(144)

    float x = mv[(size_t)bn*256 + t];
    float s1 = blockSum<8>(x, red);
    float s2 = blockSum<8>(x*x, red);
    float m  = s1 * (1.0f/256.0f);
    float vr = s2 * (1.0f/256.0f) - m*m;
    mvn[t] = (x - m) * rsqrtf(vr + LNEPS);

    float y = (t < 64) ? sca[(size_t)bn*64 + t] : 0.0f;
    float t1 = blockSum<8>(y, red);
    float t2 = blockSum<8>(y*y, red);
    float m2 = t1 * (1.0f/64.0f);
    float v2 = t2 * (1.0f/64.0f) - m2*m2;
    float rs2 = rsqrtf(v2 + LNEPS);
    if(t < 64) scn[t] = (y - m2) * rs2;
    __syncthreads();

    for(int idx = t; idx < 1024; idx += 256){
        int o = idx >> 4, i = idx & 15;
        float a = 0.0f;
#pragma unroll
        for(int c = 0; c < 16; c++) a += mvn[c*16 + i] * Wq_mv[o*16 + c];
        int hh = o & 7, mm = o >> 3;
        g_Q[((b*NH + hh)*NSEQ + n)*NCH + mm*16 + i] = a * scl;
    }
    for(int idx = t; idx < 2048; idx += 256){
        int o = idx >> 4, i = idx & 15;
        float a = 0.0f;
#pragma unroll
        for(int c = 0; c < 16; c++) a += mvn[c*16 + i] * Wkv_mv[o*16 + c];
        int kv = o >> 6, rr = o & 63, hh = rr & 7, mm = rr >> 3;
        if(kv == 0) g_K[((b*NH + hh)*NSEQ + n)*NCH + mm*16 + i] = a;
        else        g_V[((b*NH + hh)*NSEQ + n)*NCH + mm*16 + i] = a;
    }
    if(t < 128){
        float a = 0.0f;
#pragma unroll
        for(int c = 0; c < 64; c++) a += scn[c] * Wq_s[t*64 + c];
        qs[t] = a;
    }
    {
        float a = 0.0f;
#pragma unroll
        for(int c = 0; c < 64; c++) a += scn[c] * Wkv_s[t*64 + c];
        int kv = t >> 7, rr = t & 127;
        if(kv == 0) ks[rr] = a; else vs[rr] = a;
    }
    __syncthreads();

    if(t < 128){
        int hh = t & 7, ss = t >> 3;
        g_V[((b*NH + hh)*NSEQ + n)*NCH + 128 + ss] = vs[t];
    }
    if(t < 64){
        int hh = t & 7, p = t >> 3;
        float ang = (float)n * exp2f(-1.5f * (float)p);
        float cs = cosf(ang), sn = sinf(ang);
        float x1 = qs[(2*p)*8 + hh], x2 = qs[(2*p+1)*8 + hh];
        float* Qr = &g_Q[((b*NH + hh)*NSEQ + n)*NCH + 128];
        Qr[2*p]   = (x1*cs - x2*sn) * scl;
        Qr[2*p+1] = (x1*sn + x2*cs) * scl;
    } else if(t < 128){
        int u = t - 64;
        int hh = u & 7, p = u >> 3;
        float ang = (float)n * exp2f(-1.5f * (float)p);
        float cs = cosf(ang), sn = sinf(ang);
        float x1 = ks[(2*p)*8 + hh], x2 = ks[(2*p+1)*8 + hh];
        float* Kr = &g_K[((b*NH + hh)*NSEQ + n)*NCH + 128];
        Kr[2*p]   = x1*cs - x2*sn;
        Kr[2*p+1] = x1*sn + x2*cs;
    }
}

// ---------------- Kernel B: pair-scalar LN + bias projection ----------------
__global__ void bias_kernel(const float* __restrict__ pz, const unsigned int* __restrict__ msk,
                            const float* __restrict__ gamma, const float* __restrict__ beta,
                            const float* __restrict__ Wpb){
    int w = threadIdx.x >> 5, lane = threadIdx.x & 31;
    int pid = blockIdx.x * 8 + w;

    const float4* zp = (const float4*)(pz + (size_t)pid * NCZ);
    float4 z = zp[lane];
    float s1 = z.x + z.y + z.z + z.w;
    float s2 = z.x*z.x + z.y*z.y + z.z*z.z + z.w*z.w;
#pragma unroll
    for(int o=16;o;o>>=1){
        s1 += __shfl_xor_sync(0xffffffffu, s1, o);
        s2 += __shfl_xor_sync(0xffffffffu, s2, o);
    }
    float m  = s1 * (1.0f/NCZ);
    float vr = s2 * (1.0f/NCZ) - m*m;
    float rs = rsqrtf(vr + LNEPS);
    float4 g4 = ((const float4*)gamma)[lane];
    float4 b4 = ((const float4*)beta)[lane];
    float n0 = (z.x - m)*rs*g4.x + b4.x;
    float n1 = (z.y - m)*rs*g4.y + b4.y;
    float n2 = (z.z - m)*rs*g4.z + b4.z;
    float n3 = (z.w - m)*rs*g4.w + b4.w;

    float acc[8];
#pragma unroll
    for(int h = 0; h < 8; h++){
        float4 wv = ((const float4*)(Wpb + h*NCZ))[lane];
        float a = n0*wv.x + n1*wv.y + n2*wv.z + n3*wv.w;
#pragma unroll
        for(int o=16;o;o>>=1) a += __shfl_down_sync(0xffffffffu, a, o);
        acc[h] = a;
    }
    float mb = (msk[pid] != 0u) ? 0.0f : BIGF;

    __shared__ float bt[8][8];
    if(lane == 0){
#pragma unroll
        for(int h = 0; h < 8; h++) bt[w][h] = acc[h] + mb;
    }
    __syncthreads();
    if(threadIdx.x < 64){
        int h  = threadIdx.x >> 3, ww = threadIdx.x & 7;
        int p2 = blockIdx.x * 8 + ww;
        int b2 = p2 / (NSEQ*NSEQ);
        int r2 = p2 % (NSEQ*NSEQ);
        int i2 = r2 / NSEQ, j2 = r2 % NSEQ;
        g_bias[((b2*NH + h)*NSEQ + i2)*NSEQ + j2] = bt[ww][h];
    }
}

// ---------------- Kernel C: tiled attention ----------------
// Block per (b, h, q-tile of 32). 256 threads. Two-pass softmax, all tiles in smem.
__global__ void attn_kernel(){
    extern __shared__ float smem[];
    float* sQ = smem;                 // [32][SQS]
    float* sK = smem + 32*SQS;        // [32][SQS]  (reused as V tile in pass 2)
    float* sS = smem + 64*SQS;        // [32][SSS]

    int qt = blockIdx.x, h = blockIdx.y, b = blockIdx.z;
    int t = threadIdx.x;
    int q0 = qt * QT;
    size_t bh = (size_t)(b*NH + h);

    const float* Qg = g_Q + (bh*NSEQ + q0)*NCH;
    const float* Kg = g_K + bh*NSEQ*NCH;
    const float* Vg = g_V + bh*NSEQ*NCH;
    const float* Bg = g_bias + (bh*NSEQ + q0)*NSEQ;

    // load Q tile (32 rows x 144, contiguous) as float4
    for(int i4 = t; i4 < (QT*NCH)/4; i4 += 256){
        int idx = i4*4, r = idx/NCH, c = idx%NCH;
        *(float4*)(sQ + r*SQS + c) = ((const float4*)Qg)[i4];
    }

    int tq = t >> 4;       // 0..15
    int tj = t & 15;       // 0..15

    // ---- pass 1: scores ----
    for(int jt = 0; jt < NSEQ/JT; jt++){
        __syncthreads();
        const float* Kt = Kg + (size_t)(jt*JT)*NCH;
        for(int i4 = t; i4 < (JT*NCH)/4; i4 += 256){
            int idx = i4*4, r = idx/NCH, c = idx%NCH;
            *(float4*)(sK + r*SQS + c) = ((const float4*)Kt)[i4];
        }
        __syncthreads();

        float a00=0.f,a01=0.f,a10=0.f,a11=0.f;
        const float4* q0p = (const float4*)(sQ + tq*SQS);
        const float4* q1p = (const float4*)(sQ + (tq+16)*SQS);
        const float4* k0p = (const float4*)(sK + tj*SQS);
        const float4* k1p = (const float4*)(sK + (tj+16)*SQS);
#pragma unroll
        for(int c4 = 0; c4 < NCH/4; c4++){
            float4 qa = q0p[c4], qb = q1p[c4];
            float4 ka = k0p[c4], kb = k1p[c4];
            a00 += qa.x*ka.x + qa.y*ka.y + qa.z*ka.z + qa.w*ka.w;
            a01 += qa.x*kb.x + qa.y*kb.y + qa.z*kb.z + qa.w*kb.w;
            a10 += qb.x*ka.x + qb.y*ka.y + qb.z*ka.z + qb.w*ka.w;
            a11 += qb.x*kb.x + qb.y*kb.y + qb.z*kb.z + qb.w*kb.w;
        }
        int j0 = jt*JT + tj;
        sS[tq*SSS      + j0     ] = a00 + Bg[(size_t)tq*NSEQ      + j0     ];
        sS[tq*SSS      + j0 + 16] = a01 + Bg[(size_t)tq*NSEQ      + j0 + 16];
        sS[(tq+16)*SSS + j0     ] = a10 + Bg[(size_t)(tq+16)*NSEQ + j0     ];
        sS[(tq+16)*SSS + j0 + 16] = a11 + Bg[(size_t)(tq+16)*NSEQ + j0 + 16];
    }
    __syncthreads();

    // ---- softmax: warp w handles rows w*4 .. w*4+3 ----
    {
        int w = t >> 5, lane = t & 31;
#pragma unroll
        for(int rr = 0; rr < 4; rr++){
            int r = w*4 + rr;
            float* row = sS + r*SSS;
            float v[NSEQ/32];
            float mx = -1e30f;
#pragma unroll
            for(int i = 0; i < NSEQ/32; i++){
                v[i] = row[lane + 32*i];
                mx = fmaxf(mx, v[i]);
            }
#pragma unroll
            for(int o=16;o;o>>=1) mx = fmaxf(mx, __shfl_xor_sync(0xffffffffu, mx, o));
            float sm = 0.f;
#pragma unroll
            for(int i = 0; i < NSEQ/32; i++){
                v[i] = __expf(v[i] - mx);
                sm += v[i];
            }
            sm = warpSum(sm);
            float inv = 1.0f / sm;
#pragma unroll
            for(int i = 0; i < NSEQ/32; i++) row[lane + 32*i] = v[i] * inv;
        }
    }

    // ---- pass 2: O = P @ V ----
    // thread owns q rows {tq, tq+16}, channels [tj*9, tj*9+9)
    float acc0[9], acc1[9];
#pragma unroll
    for(int k = 0; k < 9; k++){ acc0[k]=0.f; acc1[k]=0.f; }

    for(int jt = 0; jt < NSEQ/JT; jt++){
        __syncthreads();
        const float* Vt = Vg + (size_t)(jt*JT)*NCH;
        for(int i4 = t; i4 < (JT*NCH)/4; i4 += 256){
            int idx = i4*4, r = idx/NCH, c = idx%NCH;
            *(float4*)(sK + r*SQS + c) = ((const float4*)Vt)[i4];
        }
        __syncthreads();

#pragma unroll 4
        for(int jj = 0; jj < JT; jj++){
            float p0 = sS[tq*SSS      + jt*JT + jj];
            float p1 = sS[(tq+16)*SSS + jt*JT + jj];
            const float* vr = sK + jj*SQS + tj*9;
#pragma unroll
            for(int k = 0; k < 9; k++){
                float vv = vr[k];
                acc0[k] += p0*vv;
                acc1[k] += p1*vv;
            }
        }
    }

    // store: g_Hb[((b*NSEQ + q)*NH + h)*NCH + c]
    {
        float* o0 = g_Hb + ((size_t)(b*NSEQ + q0 + tq   )*NH + h)*NCH + tj*9;
        float* o1 = g_Hb + ((size_t)(b*NSEQ + q0 + tq+16)*NH + h)*NCH + tj*9;
#pragma unroll
        for(int k = 0; k < 9; k++){ o0[k] = acc0[k]; o1[k] = acc1[k]; }
    }
}

// ---------------- Kernel D: output projections ----------------
// Block handles 4 (b,n) rows; weights cached in smem. 256 threads, grid 192.
__global__ void out_kernel(const float* __restrict__ Wo_mv, const float* __restrict__ Wo_s,
                           float* __restrict__ out){
    int t = threadIdx.x;
    __shared__ float wmv[16*64];    // 1024
    __shared__ float ws [64*128];   // 8192
    __shared__ float hrow[NH*NCH];  // 1152

    for(int i = t; i < 1024; i += 256) wmv[i] = Wo_mv[i];
    for(int i = t; i < 8192; i += 256) ws[i]  = Wo_s[i];

    for(int r = 0; r < 4; r++){
        int bn = blockIdx.x*4 + r;
        __syncthreads();
        for(int idx = t; idx < NH*NCH; idx += 256) hrow[idx] = g_Hb[(size_t)bn*NH*NCH + idx];
        __syncthreads();

        {
            int o = t >> 4, i = t & 15;
            float acc = 0.0f;
#pragma unroll
            for(int hh = 0; hh < 8; hh++)
#pragma unroll
                for(int mm = 0; mm < 8; mm++)
                    acc += hrow[hh*NCH + mm*16 + i] * wmv[o*64 + hh*8 + mm];
            out[(size_t)bn*256 + t] = acc;
        }
        if(t < 64){
            float acc = 0.0f;
#pragma unroll
            for(int hh = 0; hh < 8; hh++)
#pragma unroll
                for(int ss = 0; ss < 16; ss++)
                    acc += hrow[hh*NCH + 128 + ss] * ws[t*128 + hh*16 + ss];
            out[(size_t)NB*NSEQ*256 + (size_t)bn*64 + t] = acc;
        }
    }
}

// ---------------- launch ----------------
extern "C" void kernel_launch(void* const* d_in, const int* in_sizes, int n_in,
                              void* d_out, int out_size){
    const float* mv    = (const float*)d_in[0];
    const float* sca   = (const float*)d_in[1];
    const float* pz    = (const float*)d_in[2];
    const unsigned int* mask = (const unsigned int*)d_in[3];
    const float* Wq_mv = (const float*)d_in[4];
    const float* Wq_s  = (const float*)d_in[5];
    const float* Wkv_mv= (const float*)d_in[6];
    const float* Wkv_s = (const float*)d_in[7];
    const float* Wo_mv = (const float*)d_in[8];
    const float* Wo_s  = (const float*)d_in[9];
    const float* lng   = (const float*)d_in[10];
    const float* lnb   = (const float*)d_in[11];
    const float* Wpb   = (const float*)d_in[12];

    cudaFuncSetAttribute(attn_kernel, cudaFuncAttributeMaxDynamicSharedMemorySize,
                         ATTN_SMEM_FLOATS * (int)sizeof(float));

    qkv_kernel<<<NB*NSEQ, 256>>>(mv, sca, Wq_mv, Wq_s, Wkv_mv, Wkv_s);
    bias_kernel<<<(NB*NSEQ*NSEQ)/8, 256>>>(pz, mask, lng, lnb, Wpb);
    attn_kernel<<<dim3(NSEQ/QT, NH, NB), 256, ATTN_SMEM_FLOATS*sizeof(float)>>>();
    out_kernel<<<NB*NSEQ/4, 256>>>(Wo_mv, Wo_s, (float*)d_out);
}

// round 5
// speedup vs baseline: 3.2198x; 1.0652x over previous
#include <cuda_runtime.h>
#include <math.h>

#define NH 8
#define NB 2
#define NSEQ 384
#define NCZ 128
#define NCH 144            // per-head channels: 128 mv + 16 scalar
#define BIGF 100000.0f
#define LNEPS 1e-5f

#define QT 32              // q tile
#define JT 32              // j tile
#define SQS 148            // Q/K/V tile row stride (floats)
#define SSS 393            // S row stride (odd -> conflict-free column access)
#define ATTN_SMEM_FLOATS (64*SQS + 32*SSS)

// Scratch (no cudaMalloc allowed)
__device__ float g_Q[NB*NH*NSEQ*NCH];
__device__ float g_K[NB*NH*NSEQ*NCH];
__device__ float g_V[NB*NH*NSEQ*NCH];
__device__ float g_bias[NB*NH*NSEQ*NSEQ];
__device__ float g_Hb[NB*NSEQ*NH*NCH];

// ---------------- reductions ----------------
__device__ __forceinline__ float warpSum(float v){
#pragma unroll
    for(int o=16;o;o>>=1) v += __shfl_xor_sync(0xffffffffu, v, o);
    return v;
}

template<int NW>
__device__ __forceinline__ float blockSum(float v, float* red){
    int lane = threadIdx.x & 31, w = threadIdx.x >> 5;
    v = warpSum(v);
    if(lane==0) red[w] = v;
    __syncthreads();
    if(threadIdx.x < 32){
        float r = (lane < NW) ? red[lane] : 0.0f;
        r = warpSum(r);
        if(lane==0) red[0] = r;
    }
    __syncthreads();
    float r = red[0];
    __syncthreads();
    return r;
}

// ---------------- Kernel A: pln + QKV projections + rope ----------------
__global__ void qkv_kernel(const float* __restrict__ mv, const float* __restrict__ sca,
                           const float* __restrict__ Wq_mv, const float* __restrict__ Wq_s,
                           const float* __restrict__ Wkv_mv, const float* __restrict__ Wkv_s){
    int bn = blockIdx.x;
    int b = bn / NSEQ, n = bn % NSEQ;
    int t = threadIdx.x;
    __shared__ float mvn[256];
    __shared__ float scn[64];
    __shared__ float qs[128], ks[128], vs[128];
    __shared__ float red[32];
    const float scl = 1.0f/12.0f;  // 1/sqrt(144)

    float x = mv[(size_t)bn*256 + t];
    float s1 = blockSum<8>(x, red);
    float s2 = blockSum<8>(x*x, red);
    float m  = s1 * (1.0f/256.0f);
    float vr = s2 * (1.0f/256.0f) - m*m;
    mvn[t] = (x - m) * rsqrtf(vr + LNEPS);

    float y = (t < 64) ? sca[(size_t)bn*64 + t] : 0.0f;
    float t1 = blockSum<8>(y, red);
    float t2 = blockSum<8>(y*y, red);
    float m2 = t1 * (1.0f/64.0f);
    float v2 = t2 * (1.0f/64.0f) - m2*m2;
    float rs2 = rsqrtf(v2 + LNEPS);
    if(t < 64) scn[t] = (y - m2) * rs2;
    __syncthreads();

    for(int idx = t; idx < 1024; idx += 256){
        int o = idx >> 4, i = idx & 15;
        float a = 0.0f;
#pragma unroll
        for(int c = 0; c < 16; c++) a += mvn[c*16 + i] * Wq_mv[o*16 + c];
        int hh = o & 7, mm = o >> 3;
        g_Q[((b*NH + hh)*NSEQ + n)*NCH + mm*16 + i] = a * scl;
    }
    for(int idx = t; idx < 2048; idx += 256){
        int o = idx >> 4, i = idx & 15;
        float a = 0.0f;
#pragma unroll
        for(int c = 0; c < 16; c++) a += mvn[c*16 + i] * Wkv_mv[o*16 + c];
        int kv = o >> 6, rr = o & 63, hh = rr & 7, mm = rr >> 3;
        if(kv == 0) g_K[((b*NH + hh)*NSEQ + n)*NCH + mm*16 + i] = a;
        else        g_V[((b*NH + hh)*NSEQ + n)*NCH + mm*16 + i] = a;
    }
    if(t < 128){
        float a = 0.0f;
#pragma unroll
        for(int c = 0; c < 64; c++) a += scn[c] * Wq_s[t*64 + c];
        qs[t] = a;
    }
    {
        float a = 0.0f;
#pragma unroll
        for(int c = 0; c < 64; c++) a += scn[c] * Wkv_s[t*64 + c];
        int kv = t >> 7, rr = t & 127;
        if(kv == 0) ks[rr] = a; else vs[rr] = a;
    }
    __syncthreads();

    if(t < 128){
        int hh = t & 7, ss = t >> 3;
        g_V[((b*NH + hh)*NSEQ + n)*NCH + 128 + ss] = vs[t];
    }
    if(t < 64){
        int hh = t & 7, p = t >> 3;
        float ang = (float)n * exp2f(-1.5f * (float)p);
        float cs = cosf(ang), sn = sinf(ang);
        float x1 = qs[(2*p)*8 + hh], x2 = qs[(2*p+1)*8 + hh];
        float* Qr = &g_Q[((b*NH + hh)*NSEQ + n)*NCH + 128];
        Qr[2*p]   = (x1*cs - x2*sn) * scl;
        Qr[2*p+1] = (x1*sn + x2*cs) * scl;
    } else if(t < 128){
        int u = t - 64;
        int hh = u & 7, p = u >> 3;
        float ang = (float)n * exp2f(-1.5f * (float)p);
        float cs = cosf(ang), sn = sinf(ang);
        float x1 = ks[(2*p)*8 + hh], x2 = ks[(2*p+1)*8 + hh];
        float* Kr = &g_K[((b*NH + hh)*NSEQ + n)*NCH + 128];
        Kr[2*p]   = x1*cs - x2*sn;
        Kr[2*p+1] = x1*sn + x2*cs;
    }
}

// ---------------- Kernel B: bias, shuffle-free tiled version ----------------
// Block = 32 consecutive (i,j) pairs (one i, j0..j0+31). 256 threads.
// LN affine folded into projection: out = rs*(sum_c z_c*A_hc - m*G_h) + B_h
// with A = gamma*W, G_h = sum gamma_c W_hc, B_h = sum beta_c W_hc.
__global__ __launch_bounds__(256) void bias_kernel(
        const float* __restrict__ pz, const unsigned int* __restrict__ msk,
        const float* __restrict__ gamma, const float* __restrict__ beta,
        const float* __restrict__ Wpb){
    __shared__ float sZ[32*132];   // z tile, rows padded to 132
    __shared__ float sA[8*132];    // gamma*W, rows padded to 132
    __shared__ float sG[8], sB[8];
    __shared__ float sM[32];       // mean per pair
    __shared__ float sR[32];       // rstd per pair
    __shared__ float sMask[32];

    int t = threadIdx.x;
    int lane = t & 31, w = t >> 5;
    int pid0 = blockIdx.x * 32;
    int b  = pid0 / (NSEQ*NSEQ);
    int r0 = pid0 % (NSEQ*NSEQ);
    int i  = r0 / NSEQ;
    int j0 = r0 % NSEQ;

    // load z tile: 32 pairs x 128 floats = 1024 float4
    const float4* zg = (const float4*)(pz + (size_t)pid0 * NCZ);
    for(int i4 = t; i4 < 1024; i4 += 256){
        int r = i4 >> 5, c4 = i4 & 31;
        *(float4*)(sZ + r*132 + c4*4) = zg[i4];
    }
    // A = gamma * W
    for(int idx = t; idx < 1024; idx += 256){
        int h = idx >> 7, c = idx & 127;
        sA[h*132 + c] = gamma[c] * Wpb[h*NCZ + c];
    }
    // G_h, B_h: warp w reduces head h=w
    {
        float gs = 0.f, bs = 0.f;
#pragma unroll
        for(int k = 0; k < 4; k++){
            int c = lane + 32*k;
            float wv = Wpb[w*NCZ + c];
            gs += gamma[c]*wv;
            bs += beta[c]*wv;
        }
        gs = warpSum(gs); bs = warpSum(bs);
        if(lane == 0){ sG[w] = gs; sB[w] = bs; }
    }
    if(t < 32) sMask[t] = (msk[pid0 + t] != 0u) ? 0.0f : BIGF;
    __syncthreads();

    // LN stats: warp w handles pairs 4w..4w+3
#pragma unroll
    for(int rr = 0; rr < 4; rr++){
        int p = w*4 + rr;
        float4 z4 = *(const float4*)(sZ + p*132 + lane*4);
        float s1 = z4.x + z4.y + z4.z + z4.w;
        float s2 = z4.x*z4.x + z4.y*z4.y + z4.z*z4.z + z4.w*z4.w;
        s1 = warpSum(s1); s2 = warpSum(s2);
        if(lane == 0){
            float m = s1 * (1.0f/NCZ);
            float v = s2 * (1.0f/NCZ) - m*m;
            sM[p] = m;
            sR[p] = rsqrtf(v + LNEPS);
        }
    }
    __syncthreads();

    // projection: thread (pair p = t>>3, head h = t&7)
    {
        int p = t >> 3, h = t & 7;
        const float4* zp = (const float4*)(sZ + p*132);
        const float4* ap = (const float4*)(sA + h*132);
        float acc = 0.f;
#pragma unroll
        for(int c4 = 0; c4 < 32; c4++){
            float4 z4 = zp[c4], a4 = ap[c4];
            acc += z4.x*a4.x + z4.y*a4.y + z4.z*a4.z + z4.w*a4.w;
        }
        float out = sR[p]*(acc - sM[p]*sG[h]) + sB[h] + sMask[p];
        g_bias[((size_t)(b*NH + h)*NSEQ + i)*NSEQ + j0 + p] = out;
    }
}

// ---------------- Kernel C: tiled attention ----------------
// Block per (b, h, q-tile of 32). 256 threads.
__global__ __launch_bounds__(256) void attn_kernel(){
    extern __shared__ float smem[];
    float* sQ = smem;                 // [32][SQS]
    float* sK = smem + 32*SQS;        // [32][SQS]  (reused as V tile in pass 2)
    float* sS = smem + 64*SQS;        // [32][SSS]

    int qt = blockIdx.x, h = blockIdx.y, b = blockIdx.z;
    int t = threadIdx.x;
    int q0 = qt * QT;
    size_t bh = (size_t)(b*NH + h);

    const float* Qg = g_Q + (bh*NSEQ + q0)*NCH;
    const float* Kg = g_K + bh*NSEQ*NCH;
    const float* Vg = g_V + bh*NSEQ*NCH;
    const float* Bg = g_bias + (bh*NSEQ + q0)*NSEQ;

    for(int i4 = t; i4 < (QT*NCH)/4; i4 += 256){
        int idx = i4*4, r = idx/NCH, c = idx%NCH;
        *(float4*)(sQ + r*SQS + c) = ((const float4*)Qg)[i4];
    }

    int tq = t >> 4;       // 0..15
    int tj = t & 15;       // 0..15

    for(int jt = 0; jt < NSEQ/JT; jt++){
        __syncthreads();
        const float* Kt = Kg + (size_t)(jt*JT)*NCH;
        for(int i4 = t; i4 < (JT*NCH)/4; i4 += 256){
            int idx = i4*4, r = idx/NCH, c = idx%NCH;
            *(float4*)(sK + r*SQS + c) = ((const float4*)Kt)[i4];
        }
        __syncthreads();

        float a00=0.f,a01=0.f,a10=0.f,a11=0.f;
        const float4* q0p = (const float4*)(sQ + tq*SQS);
        const float4* q1p = (const float4*)(sQ + (tq+16)*SQS);
        const float4* k0p = (const float4*)(sK + tj*SQS);
        const float4* k1p = (const float4*)(sK + (tj+16)*SQS);
#pragma unroll
        for(int c4 = 0; c4 < NCH/4; c4++){
            float4 qa = q0p[c4], qb = q1p[c4];
            float4 ka = k0p[c4], kb = k1p[c4];
            a00 += qa.x*ka.x + qa.y*ka.y + qa.z*ka.z + qa.w*ka.w;
            a01 += qa.x*kb.x + qa.y*kb.y + qa.z*kb.z + qa.w*kb.w;
            a10 += qb.x*ka.x + qb.y*ka.y + qb.z*ka.z + qb.w*ka.w;
            a11 += qb.x*kb.x + qb.y*kb.y + qb.z*kb.z + qb.w*kb.w;
        }
        int j0 = jt*JT + tj;
        sS[tq*SSS      + j0     ] = a00 + Bg[(size_t)tq*NSEQ      + j0     ];
        sS[tq*SSS      + j0 + 16] = a01 + Bg[(size_t)tq*NSEQ      + j0 + 16];
        sS[(tq+16)*SSS + j0     ] = a10 + Bg[(size_t)(tq+16)*NSEQ + j0     ];
        sS[(tq+16)*SSS + j0 + 16] = a11 + Bg[(size_t)(tq+16)*NSEQ + j0 + 16];
    }
    __syncthreads();

    {
        int w = t >> 5, lane = t & 31;
#pragma unroll
        for(int rr = 0; rr < 4; rr++){
            int r = w*4 + rr;
            float* row = sS + r*SSS;
            float v[NSEQ/32];
            float mx = -1e30f;
#pragma unroll
            for(int i = 0; i < NSEQ/32; i++){
                v[i] = row[lane + 32*i];
                mx = fmaxf(mx, v[i]);
            }
#pragma unroll
            for(int o=16;o;o>>=1) mx = fmaxf(mx, __shfl_xor_sync(0xffffffffu, mx, o));
            float sm = 0.f;
#pragma unroll
            for(int i = 0; i < NSEQ/32; i++){
                v[i] = __expf(v[i] - mx);
                sm += v[i];
            }
            sm = warpSum(sm);
            float inv = 1.0f / sm;
#pragma unroll
            for(int i = 0; i < NSEQ/32; i++) row[lane + 32*i] = v[i] * inv;
        }
    }

    float acc0[9], acc1[9];
#pragma unroll
    for(int k = 0; k < 9; k++){ acc0[k]=0.f; acc1[k]=0.f; }

    for(int jt = 0; jt < NSEQ/JT; jt++){
        __syncthreads();
        const float* Vt = Vg + (size_t)(jt*JT)*NCH;
        for(int i4 = t; i4 < (JT*NCH)/4; i4 += 256){
            int idx = i4*4, r = idx/NCH, c = idx%NCH;
            *(float4*)(sK + r*SQS + c) = ((const float4*)Vt)[i4];
        }
        __syncthreads();

#pragma unroll 4
        for(int jj = 0; jj < JT; jj++){
            float p0 = sS[tq*SSS      + jt*JT + jj];
            float p1 = sS[(tq+16)*SSS + jt*JT + jj];
            const float* vr = sK + jj*SQS + tj*9;
#pragma unroll
            for(int k = 0; k < 9; k++){
                float vv = vr[k];
                acc0[k] += p0*vv;
                acc1[k] += p1*vv;
            }
        }
    }

    {
        float* o0 = g_Hb + ((size_t)(b*NSEQ + q0 + tq   )*NH + h)*NCH + tj*9;
        float* o1 = g_Hb + ((size_t)(b*NSEQ + q0 + tq+16)*NH + h)*NCH + tj*9;
#pragma unroll
        for(int k = 0; k < 9; k++){ o0[k] = acc0[k]; o1[k] = acc1[k]; }
    }
}

// ---------------- Kernel D: output projections ----------------
// One block per (b,n). 256 threads. Weights staged in smem.
__global__ __launch_bounds__(256) void out_kernel(
        const float* __restrict__ Wo_mv, const float* __restrict__ Wo_s,
        float* __restrict__ out){
    int bn = blockIdx.x;
    int t = threadIdx.x;
    __shared__ float wmv[16*64];    // 4KB
    __shared__ float ws [64*128];   // 32KB
    __shared__ float hrow[NH*NCH];  // 1152 floats

    for(int i = t; i < 1024; i += 256) wmv[i] = Wo_mv[i];
    for(int i4 = t; i4 < 2048; i4 += 256)
        *(float4*)(ws + i4*4) = ((const float4*)Wo_s)[i4];
    for(int i4 = t; i4 < 288; i4 += 256)
        *(float4*)(hrow + i4*4) = ((const float4*)(g_Hb + (size_t)bn*NH*NCH))[i4];
    __syncthreads();

    {
        int o = t >> 4, i = t & 15;
        float acc = 0.0f;
#pragma unroll
        for(int hh = 0; hh < 8; hh++)
#pragma unroll
            for(int mm = 0; mm < 8; mm++)
                acc += hrow[hh*NCH + mm*16 + i] * wmv[o*64 + hh*8 + mm];
        out[(size_t)bn*256 + t] = acc;
    }
    if(t < 64){
        float acc = 0.0f;
#pragma unroll
        for(int hh = 0; hh < 8; hh++)
#pragma unroll
            for(int ss = 0; ss < 16; ss++)
                acc += hrow[hh*NCH + 128 + ss] * ws[t*128 + hh*16 + ss];
        out[(size_t)NB*NSEQ*256 + (size_t)bn*64 + t] = acc;
    }
}

// ---------------- launch ----------------
extern "C" void kernel_launch(void* const* d_in, const int* in_sizes, int n_in,
                              void* d_out, int out_size){
    const float* mv    = (const float*)d_in[0];
    const float* sca   = (const float*)d_in[1];
    const float* pz    = (const float*)d_in[2];
    const unsigned int* mask = (const unsigned int*)d_in[3];
    const float* Wq_mv = (const float*)d_in[4];
    const float* Wq_s  = (const float*)d_in[5];
    const float* Wkv_mv= (const float*)d_in[6];
    const float* Wkv_s = (const float*)d_in[7];
    const float* Wo_mv = (const float*)d_in[8];
    const float* Wo_s  = (const float*)d_in[9];
    const float* lng   = (const float*)d_in[10];
    const float* lnb   = (const float*)d_in[11];
    const float* Wpb   = (const float*)d_in[12];

    cudaFuncSetAttribute(attn_kernel, cudaFuncAttributeMaxDynamicSharedMemorySize,
                         ATTN_SMEM_FLOATS * (int)sizeof(float));

    qkv_kernel<<<NB*NSEQ, 256>>>(mv, sca, Wq_mv, Wq_s, Wkv_mv, Wkv_s);
    bias_kernel<<<(NB*NSEQ*NSEQ)/32, 256>>>(pz, mask, lng, lnb, Wpb);
    attn_kernel<<<dim3(NSEQ/QT, NH, NB), 256, ATTN_SMEM_FLOATS*sizeof(float)>>>();
    out_kernel<<<NB*NSEQ, 256>>>(Wo_mv, Wo_s, (float*)d_out);
}

// round 8
// speedup vs baseline: 3.3941x; 1.0541x over previous
#include <cuda_runtime.h>
#include <math.h>

#define NH 8
#define NB 2
#define NSEQ 384
#define NCZ 128
#define NCH 144            // per-head channels: 128 mv + 16 scalar
#define BIGF 100000.0f
#define LNEPS 1e-5f

#define QT 32              // q tile
#define JTT 64             // j tile
#define NJT (NSEQ/JTT)     // 6

// smem strides (floats)
#define SQP 36             // sQ [144][36]  (32 cols + pad, float4-aligned)
#define SKP 68             // sK [144][68]  (64 cols + pad, float4-aligned)
#define SVP 148            // sV [64][148]
#define SPP 68             // sP [32][68]
#define ATTN_SMEM_FLOATS (144*SQP + 144*SKP + 64*SVP + 32*SPP)

// Scratch (no cudaMalloc allowed)
__device__ float g_Q[NB*NH*NCH*NSEQ];    // channel-major [b][h][c][n]
__device__ float g_K[NB*NH*NCH*NSEQ];    // channel-major [b][h][c][n]
__device__ float g_V[NB*NH*NSEQ*NCH];    // row-major    [b][h][n][c]
__device__ float g_bias[NB*NH*NSEQ*NSEQ];
__device__ float g_Hb[NB*NSEQ*NH*NCH];

// ---------------- reductions ----------------
__device__ __forceinline__ float warpSum(float v){
#pragma unroll
    for(int o=16;o;o>>=1) v += __shfl_xor_sync(0xffffffffu, v, o);
    return v;
}

template<int NW>
__device__ __forceinline__ float blockSum(float v, float* red){
    int lane = threadIdx.x & 31, w = threadIdx.x >> 5;
    v = warpSum(v);
    if(lane==0) red[w] = v;
    __syncthreads();
    if(threadIdx.x < 32){
        float r = (lane < NW) ? red[lane] : 0.0f;
        r = warpSum(r);
        if(lane==0) red[0] = r;
    }
    __syncthreads();
    float r = red[0];
    __syncthreads();
    return r;
}

// reduce over the 16-lane tx-group (lanes with same ty)
__device__ __forceinline__ float grpMax(float v){
#pragma unroll
    for(int o=8;o;o>>=1) v = fmaxf(v, __shfl_xor_sync(0xffffffffu, v, o));
    return v;
}
__device__ __forceinline__ float grpSum(float v){
#pragma unroll
    for(int o=8;o;o>>=1) v += __shfl_xor_sync(0xffffffffu, v, o);
    return v;
}

// ---------------- Kernel A: pln + QKV projections + rope ----------------
__global__ void qkv_kernel(const float* __restrict__ mv, const float* __restrict__ sca,
                           const float* __restrict__ Wq_mv, const float* __restrict__ Wq_s,
                           const float* __restrict__ Wkv_mv, const float* __restrict__ Wkv_s){
    int bn = blockIdx.x;
    int b = bn / NSEQ, n = bn % NSEQ;
    int t = threadIdx.x;
    __shared__ float mvn[256];
    __shared__ float scn[64];
    __shared__ float qs[128], ks[128], vs[128];
    __shared__ float red[32];
    const float scl = 1.0f/12.0f;  // 1/sqrt(144)

    float x = mv[(size_t)bn*256 + t];
    float s1 = blockSum<8>(x, red);
    float s2 = blockSum<8>(x*x, red);
    float m  = s1 * (1.0f/256.0f);
    float vr = s2 * (1.0f/256.0f) - m*m;
    mvn[t] = (x - m) * rsqrtf(vr + LNEPS);

    float y = (t < 64) ? sca[(size_t)bn*64 + t] : 0.0f;
    float t1 = blockSum<8>(y, red);
    float t2 = blockSum<8>(y*y, red);
    float m2 = t1 * (1.0f/64.0f);
    float v2 = t2 * (1.0f/64.0f) - m2*m2;
    float rs2 = rsqrtf(v2 + LNEPS);
    if(t < 64) scn[t] = (y - m2) * rs2;
    __syncthreads();

    // q_mv -> g_Q channel-major
    for(int idx = t; idx < 1024; idx += 256){
        int o = idx >> 4, i = idx & 15;
        float a = 0.0f;
#pragma unroll
        for(int c = 0; c < 16; c++) a += mvn[c*16 + i] * Wq_mv[o*16 + c];
        int hh = o & 7, mm = o >> 3;
        g_Q[((size_t)(b*NH + hh)*NCH + mm*16 + i)*NSEQ + n] = a * scl;
    }
    // kv_mv -> g_K channel-major, g_V row-major
    for(int idx = t; idx < 2048; idx += 256){
        int o = idx >> 4, i = idx & 15;
        float a = 0.0f;
#pragma unroll
        for(int c = 0; c < 16; c++) a += mvn[c*16 + i] * Wkv_mv[o*16 + c];
        int kv = o >> 6, rr = o & 63, hh = rr & 7, mm = rr >> 3;
        if(kv == 0) g_K[((size_t)(b*NH + hh)*NCH + mm*16 + i)*NSEQ + n] = a;
        else        g_V[((size_t)(b*NH + hh)*NSEQ + n)*NCH + mm*16 + i] = a;
    }
    if(t < 128){
        float a = 0.0f;
#pragma unroll
        for(int c = 0; c < 64; c++) a += scn[c] * Wq_s[t*64 + c];
        qs[t] = a;
    }
    {
        float a = 0.0f;
#pragma unroll
        for(int c = 0; c < 64; c++) a += scn[c] * Wkv_s[t*64 + c];
        int kv = t >> 7, rr = t & 127;
        if(kv == 0) ks[rr] = a; else vs[rr] = a;
    }
    __syncthreads();

    if(t < 128){
        int hh = t & 7, ss = t >> 3;
        g_V[((size_t)(b*NH + hh)*NSEQ + n)*NCH + 128 + ss] = vs[t];
    }
    if(t < 64){
        int hh = t & 7, p = t >> 3;
        float ang = (float)n * exp2f(-1.5f * (float)p);
        float cs = cosf(ang), sn = sinf(ang);
        float x1 = qs[(2*p)*8 + hh], x2 = qs[(2*p+1)*8 + hh];
        size_t base = ((size_t)(b*NH + hh)*NCH + 128);
        g_Q[(base + 2*p  )*NSEQ + n] = (x1*cs - x2*sn) * scl;
        g_Q[(base + 2*p+1)*NSEQ + n] = (x1*sn + x2*cs) * scl;
    } else if(t < 128){
        int u = t - 64;
        int hh = u & 7, p = u >> 3;
        float ang = (float)n * exp2f(-1.5f * (float)p);
        float cs = cosf(ang), sn = sinf(ang);
        float x1 = ks[(2*p)*8 + hh], x2 = ks[(2*p+1)*8 + hh];
        size_t base = ((size_t)(b*NH + hh)*NCH + 128);
        g_K[(base + 2*p  )*NSEQ + n] = x1*cs - x2*sn;
        g_K[(base + 2*p+1)*NSEQ + n] = x1*sn + x2*cs;
    }
}

// ---------------- Kernel B: bias (unchanged from R5) ----------------
__global__ __launch_bounds__(256) void bias_kernel(
        const float* __restrict__ pz, const unsigned int* __restrict__ msk,
        const float* __restrict__ gamma, const float* __restrict__ beta,
        const float* __restrict__ Wpb){
    __shared__ float sZ[32*132];
    __shared__ float sA[8*132];
    __shared__ float sG[8], sB[8];
    __shared__ float sM[32];
    __shared__ float sR[32];
    __shared__ float sMask[32];

    int t = threadIdx.x;
    int lane = t & 31, w = t >> 5;
    int pid0 = blockIdx.x * 32;
    int b  = pid0 / (NSEQ*NSEQ);
    int r0 = pid0 % (NSEQ*NSEQ);
    int i  = r0 / NSEQ;
    int j0 = r0 % NSEQ;

    const float4* zg = (const float4*)(pz + (size_t)pid0 * NCZ);
    for(int i4 = t; i4 < 1024; i4 += 256){
        int r = i4 >> 5, c4 = i4 & 31;
        *(float4*)(sZ + r*132 + c4*4) = zg[i4];
    }
    for(int idx = t; idx < 1024; idx += 256){
        int h = idx >> 7, c = idx & 127;
        sA[h*132 + c] = gamma[c] * Wpb[h*NCZ + c];
    }
    {
        float gs = 0.f, bs = 0.f;
#pragma unroll
        for(int k = 0; k < 4; k++){
            int c = lane + 32*k;
            float wv = Wpb[w*NCZ + c];
            gs += gamma[c]*wv;
            bs += beta[c]*wv;
        }
        gs = warpSum(gs); bs = warpSum(bs);
        if(lane == 0){ sG[w] = gs; sB[w] = bs; }
    }
    if(t < 32) sMask[t] = (msk[pid0 + t] != 0u) ? 0.0f : BIGF;
    __syncthreads();

#pragma unroll
    for(int rr = 0; rr < 4; rr++){
        int p = w*4 + rr;
        float4 z4 = *(const float4*)(sZ + p*132 + lane*4);
        float s1 = z4.x + z4.y + z4.z + z4.w;
        float s2 = z4.x*z4.x + z4.y*z4.y + z4.z*z4.z + z4.w*z4.w;
        s1 = warpSum(s1); s2 = warpSum(s2);
        if(lane == 0){
            float m = s1 * (1.0f/NCZ);
            float v = s2 * (1.0f/NCZ) - m*m;
            sM[p] = m;
            sR[p] = rsqrtf(v + LNEPS);
        }
    }
    __syncthreads();

    {
        int p = t >> 3, h = t & 7;
        const float4* zp = (const float4*)(sZ + p*132);
        const float4* ap = (const float4*)(sA + h*132);
        float acc = 0.f;
#pragma unroll
        for(int c4 = 0; c4 < 32; c4++){
            float4 z4 = zp[c4], a4 = ap[c4];
            acc += z4.x*a4.x + z4.y*a4.y + z4.z*a4.z + z4.w*a4.w;
        }
        float out = sR[p]*(acc - sM[p]*sG[h]) + sB[h] + sMask[p];
        g_bias[((size_t)(b*NH + h)*NSEQ + i)*NSEQ + j0 + p] = out;
    }
}

// ---------------- Kernel C: online-softmax attention, outer-product QK ----------------
// Block per (b,h,qtile32). 256 threads = (ty 0..15) x (tx 0..15).
// Thread: S tile rows {ty*2, ty*2+1} x cols {tx*4..tx*4+3}; O rows same x channels tx*9..+8.
__global__ __launch_bounds__(256) void attn_kernel(){
    extern __shared__ float smem[];
    float* sQ = smem;                       // [144][SQP]
    float* sK = sQ + 144*SQP;               // [144][SKP]
    float* sV = sK + 144*SKP;               // [64][SVP]
    float* sP = sV + 64*SVP;                // [32][SPP]

    int qt = blockIdx.x, h = blockIdx.y, b = blockIdx.z;
    int t = threadIdx.x;
    int ty = t >> 4, tx = t & 15;
    int q0 = qt * QT;
    size_t bh = (size_t)(b*NH + h);

    const float* Qg = g_Q + bh*NCH*NSEQ;    // [c][n]
    const float* Kg = g_K + bh*NCH*NSEQ;    // [c][n]
    const float* Vg = g_V + bh*NSEQ*NCH;    // [n][c]
    const float* Bg = g_bias + (bh*NSEQ + q0)*NSEQ;

    // load Q tile: 144 ch x 32 q
    for(int i4 = t; i4 < 144*8; i4 += 256){
        int c = i4 >> 3, qq = i4 & 7;
        *(float4*)(sQ + c*SQP + qq*4) = *(const float4*)(Qg + (size_t)c*NSEQ + q0 + qq*4);
    }

    int r0 = ty*2, r1 = ty*2 + 1;
    float m0 = -1e30f, m1 = -1e30f, l0 = 0.f, l1 = 0.f;
    float O0[9], O1[9];
#pragma unroll
    for(int k = 0; k < 9; k++){ O0[k]=0.f; O1[k]=0.f; }

    for(int jt = 0; jt < NJT; jt++){
        int j0 = jt * JTT;
        __syncthreads();   // previous AV done before overwriting K/V
        // K tile: 144 ch x 64 j
        for(int i4 = t; i4 < 144*16; i4 += 256){
            int c = i4 >> 4, jj = i4 & 15;
            *(float4*)(sK + c*SKP + jj*4) = *(const float4*)(Kg + (size_t)c*NSEQ + j0 + jj*4);
        }
        // V tile: 64 j x 144 ch
        for(int i4 = t; i4 < 64*36; i4 += 256){
            int r = i4/36, c4 = i4%36;
            *(float4*)(sV + r*SVP + c4*4) = *(const float4*)(Vg + (size_t)(j0+r)*NCH + c4*4);
        }
        __syncthreads();

        // S: 2x4 per thread, outer product over channels
        float s00=0,s01=0,s02=0,s03=0,s10=0,s11=0,s12=0,s13=0;
#pragma unroll 8
        for(int c = 0; c < NCH; c++){
            float qa = sQ[c*SQP + r0];
            float qb = sQ[c*SQP + r1];
            float4 k4 = *(float4*)(sK + c*SKP + tx*4);
            s00 += qa*k4.x; s01 += qa*k4.y; s02 += qa*k4.z; s03 += qa*k4.w;
            s10 += qb*k4.x; s11 += qb*k4.y; s12 += qb*k4.z; s13 += qb*k4.w;
        }
        {
            float4 b0 = *(const float4*)(Bg + (size_t)r0*NSEQ + j0 + tx*4);
            float4 b1 = *(const float4*)(Bg + (size_t)r1*NSEQ + j0 + tx*4);
            s00+=b0.x; s01+=b0.y; s02+=b0.z; s03+=b0.w;
            s10+=b1.x; s11+=b1.y; s12+=b1.z; s13+=b1.w;
        }
        // online softmax update
        float nm0 = grpMax(fmaxf(fmaxf(s00,s01), fmaxf(s02,s03)));
        float nm1 = grpMax(fmaxf(fmaxf(s10,s11), fmaxf(s12,s13)));
        nm0 = fmaxf(m0, nm0);
        nm1 = fmaxf(m1, nm1);
        float a0 = __expf(m0 - nm0);
        float a1 = __expf(m1 - nm1);
        float p00 = __expf(s00-nm0), p01 = __expf(s01-nm0), p02 = __expf(s02-nm0), p03 = __expf(s03-nm0);
        float p10 = __expf(s10-nm1), p11 = __expf(s11-nm1), p12 = __expf(s12-nm1), p13 = __expf(s13-nm1);
        float ps0 = grpSum(p00+p01+p02+p03);
        float ps1 = grpSum(p10+p11+p12+p13);
        l0 = l0*a0 + ps0;  m0 = nm0;
        l1 = l1*a1 + ps1;  m1 = nm1;
#pragma unroll
        for(int k = 0; k < 9; k++){ O0[k] *= a0; O1[k] *= a1; }
        *(float4*)(sP + r0*SPP + tx*4) = make_float4(p00,p01,p02,p03);
        *(float4*)(sP + r1*SPP + tx*4) = make_float4(p10,p11,p12,p13);
        __syncthreads();

        // AV: accumulate over the 64 keys of this tile
#pragma unroll 4
        for(int jj = 0; jj < JTT; jj++){
            float p0 = sP[r0*SPP + jj];
            float p1 = sP[r1*SPP + jj];
            const float* vr = sV + jj*SVP + tx*9;
#pragma unroll
            for(int k = 0; k < 9; k++){
                float vv = vr[k];
                O0[k] += p0*vv;
                O1[k] += p1*vv;
            }
        }
    }

    float inv0 = 1.0f/l0, inv1 = 1.0f/l1;
    float* o0 = g_Hb + ((size_t)(b*NSEQ + q0 + r0)*NH + h)*NCH + tx*9;
    float* o1 = g_Hb + ((size_t)(b*NSEQ + q0 + r1)*NH + h)*NCH + tx*9;
#pragma unroll
    for(int k = 0; k < 9; k++){ o0[k] = O0[k]*inv0; o1[k] = O1[k]*inv1; }
}

// ---------------- Kernel D: output projections ----------------
__global__ __launch_bounds__(256) void out_kernel(
        const float* __restrict__ Wo_mv, const float* __restrict__ Wo_s,
        float* __restrict__ out){
    int bn = blockIdx.x;
    int t = threadIdx.x;
    __shared__ float wmv[16*64];
    __shared__ float ws [64*128];
    __shared__ float hrow[NH*NCH];

    for(int i = t; i < 1024; i += 256) wmv[i] = Wo_mv[i];
    for(int i4 = t; i4 < 2048; i4 += 256)
        *(float4*)(ws + i4*4) = ((const float4*)Wo_s)[i4];
    for(int i4 = t; i4 < 288; i4 += 256)
        *(float4*)(hrow + i4*4) = ((const float4*)(g_Hb + (size_t)bn*NH*NCH))[i4];
    __syncthreads();

    {
        int o = t >> 4, i = t & 15;
        float acc = 0.0f;
#pragma unroll
        for(int hh = 0; hh < 8; hh++)
#pragma unroll
            for(int mm = 0; mm < 8; mm++)
                acc += hrow[hh*NCH + mm*16 + i] * wmv[o*64 + hh*8 + mm];
        out[(size_t)bn*256 + t] = acc;
    }
    if(t < 64){
        float acc = 0.0f;
#pragma unroll
        for(int hh = 0; hh < 8; hh++)
#pragma unroll
            for(int ss = 0; ss < 16; ss++)
                acc += hrow[hh*NCH + 128 + ss] * ws[t*128 + hh*16 + ss];
        out[(size_t)NB*NSEQ*256 + (size_t)bn*64 + t] = acc;
    }
}

// ---------------- launch ----------------
extern "C" void kernel_launch(void* const* d_in, const int* in_sizes, int n_in,
                              void* d_out, int out_size){
    const float* mv    = (const float*)d_in[0];
    const float* sca   = (const float*)d_in[1];
    const float* pz    = (const float*)d_in[2];
    const unsigned int* mask = (const unsigned int*)d_in[3];
    const float* Wq_mv = (const float*)d_in[4];
    const float* Wq_s  = (const float*)d_in[5];
    const float* Wkv_mv= (const float*)d_in[6];
    const float* Wkv_s = (const float*)d_in[7];
    const float* Wo_mv = (const float*)d_in[8];
    const float* Wo_s  = (const float*)d_in[9];
    const float* lng   = (const float*)d_in[10];
    const float* lnb   = (const float*)d_in[11];
    const float* Wpb   = (const float*)d_in[12];

    cudaFuncSetAttribute(attn_kernel, cudaFuncAttributeMaxDynamicSharedMemorySize,
                         ATTN_SMEM_FLOATS * (int)sizeof(float));

    qkv_kernel<<<NB*NSEQ, 256>>>(mv, sca, Wq_mv, Wq_s, Wkv_mv, Wkv_s);
    bias_kernel<<<(NB*NSEQ*NSEQ)/32, 256>>>(pz, mask, lng, lnb, Wpb);
    attn_kernel<<<dim3(NSEQ/QT, NH, NB), 256, ATTN_SMEM_FLOATS*sizeof(float)>>>();
    out_kernel<<<NB*NSEQ, 256>>>(Wo_mv, Wo_s, (float*)d_out);
}